// round 16
// baseline (speedup 1.0000x reference)
#include <cuda_runtime.h>
#include <cstdint>

#define B_   64
#define T_   4096
#define H_   128
#define C1_  64
#define NCLS_ 40
#define NCTA_ 128

// ---------------- device scratch (no allocations allowed) ----------------
__device__ float g_part[NCTA_][9];     // per-CTA partial moments of x
__device__ unsigned int g_bar  = 0;    // grid barrier counter (reset in-kernel)
__device__ unsigned int g_done = 0;

// ---------------- helpers ----------------
__device__ __forceinline__ float tanh_fast(float v) {
    return __fdividef(2.f, 1.f + __expf(-2.f * v)) - 1.f;
}
__device__ __forceinline__ float sig_fast(float v) {
    return __fdividef(1.f, 1.f + __expf(-v));
}
__device__ __forceinline__ uint32_t smem_u32(const void* p) {
    return (uint32_t)__cvta_generic_to_shared(p);
}
__device__ __forceinline__ uint32_t mapa_u32(uint32_t addr, uint32_t rank) {
    uint32_t r;
    asm("mapa.shared::cluster.u32 %0, %1, %2;" : "=r"(r) : "r"(addr), "r"(rank));
    return r;
}
__device__ __forceinline__ void st_async_remote_b64(uint32_t addr, unsigned long long v,
                                                    uint32_t mbar) {
    asm volatile("st.async.shared::cluster.mbarrier::complete_tx::bytes.b64 [%0], %1, [%2];"
                 :: "r"(addr), "l"(v), "r"(mbar) : "memory");
}
__device__ __forceinline__ void mbar_init(uint32_t addr, uint32_t cnt) {
    asm volatile("mbarrier.init.shared.b64 [%0], %1;" :: "r"(addr), "r"(cnt) : "memory");
}
__device__ __forceinline__ void mbar_expect_tx(uint32_t addr, uint32_t bytes) {
    asm volatile("mbarrier.arrive.expect_tx.shared.b64 _, [%0], %1;"
                 :: "r"(addr), "r"(bytes) : "memory");
}
__device__ __forceinline__ void mbar_wait(uint32_t addr, uint32_t parity) {
    asm volatile(
        "{\n\t"
        ".reg .pred P;\n\t"
        "WAITLOOP_%=:\n\t"
        "mbarrier.try_wait.parity.acquire.cta.shared::cta.b64 P, [%0], %1, 0x989680;\n\t"
        "@P bra.uni WAITDONE_%=;\n\t"
        "bra.uni WAITLOOP_%=;\n\t"
        "WAITDONE_%=:\n\t"
        "}\n\t"
        :: "r"(addr), "r"(parity) : "memory");
}
__device__ __forceinline__ void cluster_barrier() {
    asm volatile("barrier.cluster.arrive.aligned;" ::: "memory");
    asm volatile("barrier.cluster.wait.aligned;" ::: "memory");
}
__device__ __forceinline__ unsigned long long pack2(float lo, float hi) {
    unsigned long long u;
    asm("mov.b64 %0, {%1, %2};" : "=l"(u) : "f"(lo), "f"(hi));
    return u;
}
__device__ __forceinline__ void unpack2(float& lo, float& hi, unsigned long long u) {
    asm("mov.b64 {%0, %1}, %2;" : "=f"(lo), "=f"(hi) : "l"(u));
}
__device__ __forceinline__ void ffma2(unsigned long long& acc, unsigned long long a,
                                      unsigned long long b) {
    asm("fma.rn.f32x2 %0, %1, %2, %3;" : "=l"(acc) : "l"(a), "l"(b), "l"(acc));
}
__device__ __forceinline__ unsigned long long fadd2(unsigned long long a,
                                                    unsigned long long b) {
    unsigned long long r;
    asm("add.rn.f32x2 %0, %1, %2;" : "=l"(r) : "l"(a), "l"(b));
    return r;
}
union F4U2 { float4 v; unsigned long long u[2]; };

// ---------------- single fused kernel ----------------
// 128 CTAs, cluster=(2,1,1): blockIdx.x>>1 = batch row, blockIdx.x&1 = hidden half.
// ROW layout champion + serial-chain cuts: gi in-register, b64-paired st.async
// (half the mbarrier tx RMWs), expect_tx re-arm off the wait->matmul path,
// packed accumulator combine.
__global__ void __cluster_dims__(2, 1, 1) __launch_bounds__(256, 1)
lstm_kernel(const float* __restrict__ x,
            const float* __restrict__ conv_w, const float* __restrict__ conv_b,
            const float* __restrict__ bn_g,   const float* __restrict__ bn_b,
            const float* __restrict__ w_ih, const float* __restrict__ b_ih,
            const float* __restrict__ w_hh, const float* __restrict__ b_hh,
            const float* __restrict__ out_w, const float* __restrict__ out_b,
            const float* __restrict__ h0, const float* __restrict__ c0,
            float* __restrict__ out) {
    __shared__ __align__(16) float h_s[2][H_];   // double-buffered full h
    __shared__ __align__(16) float y_s[C1_];     // conv output (2-BAR safe)
    __shared__ float act_s[256];                 // activated gates
    __shared__ float scw[C1_ * 3];               // folded conv weights
    __shared__ float scb[C1_];
    __shared__ float wred[8][9];
    __shared__ __align__(8) unsigned long long mbar[1];

    const int tid  = threadIdx.x;
    const int b    = blockIdx.x >> 1;
    const int half = blockIdx.x & 1;
    const int lane = tid & 31;
    const int wid  = tid >> 5;

    // ======== prologue A: moments of this CTA's half of row b ========
    {
        float s[9];
        #pragma unroll
        for (int j = 0; j < 9; j++) s[j] = 0.f;
        const float* xr = x + ((size_t)b * T_ + half * (T_ / 2)) * 3;
        #pragma unroll 1
        for (int i = tid; i < T_ / 2; i += 256) {
            float a = xr[i*3+0], bb = xr[i*3+1], c = xr[i*3+2];
            s[0] += a;     s[1] += bb;    s[2] += c;
            s[3] += a*a;   s[4] += a*bb;  s[5] += a*c;
            s[6] += bb*bb; s[7] += bb*c;  s[8] += c*c;
        }
        #pragma unroll
        for (int j = 0; j < 9; j++)
            #pragma unroll
            for (int o = 16; o > 0; o >>= 1)
                s[j] += __shfl_xor_sync(0xFFFFFFFFu, s[j], o);
        if (lane == 0)
            #pragma unroll
            for (int j = 0; j < 9; j++) wred[wid][j] = s[j];
        __syncthreads();
        if (tid < 9) {
            float t = 0.f;
            #pragma unroll
            for (int w = 0; w < 8; w++) t += wred[w][tid];
            g_part[blockIdx.x][tid] = t;
            __threadfence();
        }
        __syncthreads();
        if (tid == 0) atomicAdd(&g_bar, 1u);
    }

    // ======== load LSTM weights (overlaps the grid-barrier wait) ========
    const int q  = tid >> 6;         // gate: 0=i 1=f 2=g 3=o
    const int jj = tid & 63;         // hidden unit within half [0,64)
    const int r  = q * H_ + half * 64 + jj;
    const int own_off  = half * 64;
    const int peer_off = own_off ^ 64;

    unsigned long long whh_own[32], whh_per[32];
    {
        const float2* wo = (const float2*)(w_hh + (size_t)r * H_ + own_off);
        const float2* wp = (const float2*)(w_hh + (size_t)r * H_ + peer_off);
        #pragma unroll
        for (int k = 0; k < 32; k++) {
            float2 a = wo[k]; whh_own[k] = pack2(a.x, a.y);
            float2 c = wp[k]; whh_per[k] = pack2(c.x, c.y);
        }
    }
    unsigned long long wih2[C1_ / 2];
    #pragma unroll
    for (int k = 0; k < C1_ / 2; k++) {
        float2 w = ((const float2*)(w_ih + (size_t)r * C1_))[k];
        wih2[k] = pack2(w.x, w.y);
    }
    const float bias = b_ih[r] + b_hh[r];

    // ======== prologue B: grid barrier + BN fold ========
    if (tid == 0) { while (atomicAdd(&g_bar, 0u) < (unsigned)NCTA_) {} }
    __syncthreads();
    __threadfence();
    if (tid < C1_) {
        float st[9];
        #pragma unroll
        for (int j = 0; j < 9; j++) {
            float t = 0.f;
            #pragma unroll 8
            for (int i = 0; i < NCTA_; i++) t += g_part[i][j];
            st[j] = t;
        }
        const float N = (float)(B_ * T_);
        float m0 = st[0]/N, m1 = st[1]/N, m2 = st[2]/N;
        float C00 = st[3]/N - m0*m0, C01 = st[4]/N - m0*m1, C02 = st[5]/N - m0*m2;
        float C11 = st[6]/N - m1*m1, C12 = st[7]/N - m1*m2, C22 = st[8]/N - m2*m2;
        float w0 = conv_w[tid*3+0], w1 = conv_w[tid*3+1], w2 = conv_w[tid*3+2];
        float mean = w0*m0 + w1*m1 + w2*m2 + conv_b[tid];
        float var  = w0*w0*C00 + w1*w1*C11 + w2*w2*C22
                   + 2.f*(w0*w1*C01 + w0*w2*C02 + w1*w2*C12);
        float sc = bn_g[tid] * rsqrtf(var + 1e-5f);
        scw[tid*3+0] = w0 * sc;
        scw[tid*3+1] = w1 * sc;
        scw[tid*3+2] = w2 * sc;
        scb[tid]     = conv_b[tid] * sc + (bn_b[tid] - mean * sc);
    }
    if (tid == 0) {   // counter reset for the next (graph-replayed) launch
        unsigned d = atomicAdd(&g_done, 1u);
        if (d == (unsigned)(NCTA_ - 1)) { g_bar = 0u; __threadfence(); g_done = 0u; }
    }
    __syncthreads();

    // ======== state init ========
    float creg = 0.f;
    if (tid < 64) creg = c0[b * H_ + half * 64 + tid];
    if (tid < H_) h_s[0][tid] = h0[b * H_ + tid];

    const float* xb = x + (size_t)b * T_ * 3;
    float px0 = 0.f, px1 = 0.f, px2 = 0.f;   // x(t+1) during step t
    if (tid >= 64 && tid < 128) {            // conv lanes, channel jj
        float v = fmaf(scw[jj*3+2], xb[2],
                  fmaf(scw[jj*3+1], xb[1],
                  fmaf(scw[jj*3+0], xb[0], scb[jj])));
        y_s[jj] = fmaxf(v, 0.f);
        px0 = xb[3]; px1 = xb[4]; px2 = xb[5];
    }

    const uint32_t mbar_a    = smem_u32(mbar);
    const uint32_t peer_mbar = mapa_u32(mbar_a, (uint32_t)(half ^ 1));
    const uint32_t peer_h    = mapa_u32(smem_u32(&h_s[0][0]), (uint32_t)(half ^ 1));

    if (tid == 0) mbar_init(mbar_a, 1);
    __syncthreads();
    cluster_barrier();   // mbar init visible cluster-wide before any st.async
    if (tid == 0) mbar_expect_tx(mbar_a, 64 * 4);   // phase 0

    uint32_t parity = 0;

    #pragma unroll 1
    for (int t = 0; t < T_; t++) {
        const int cur = t & 1;
        const int nxt = cur ^ 1;

        // ---- pre-wait: bias + W_ih*y(t) + W_hh_own*h_own(t) ----
        unsigned long long acc0 = pack2(bias, 0.f), acc1 = pack2(0.f, 0.f);
        const float4* y4 = (const float4*)y_s;
        #pragma unroll
        for (int c2 = 0; c2 < C1_ / 4; c2++) {
            F4U2 yv; yv.v = y4[c2];
            ffma2(acc0, wih2[2*c2],     yv.u[0]);
            ffma2(acc1, wih2[2*c2 + 1], yv.u[1]);
        }
        const float4* ho4 = (const float4*)&h_s[cur][own_off];
        #pragma unroll
        for (int k2 = 0; k2 < 16; k2++) {
            F4U2 hv; hv.v = ho4[k2];
            ffma2(acc0, whh_own[2*k2],     hv.u[0]);
            ffma2(acc1, whh_own[2*k2 + 1], hv.u[1]);
        }
        // x(t+2) prefetch issue (consumed next step)
        float nx0 = 0.f, nx1 = 0.f, nx2 = 0.f;
        if (tid >= 64 && tid < 128 && t + 2 < T_) {
            const float* xp = xb + (size_t)(t + 2) * 3;
            nx0 = xp[0]; nx1 = xp[1]; nx2 = xp[2];
        }

        // ---- wait for peer half of h(t) ----
        if (t > 0) mbar_wait(mbar_a, parity);
        // ---- post-wait: peer-half matmul, fresh accumulators ----
        unsigned long long acc2 = pack2(0.f, 0.f), acc3 = pack2(0.f, 0.f);
        const float4* hp4 = (const float4*)&h_s[cur][peer_off];
        #pragma unroll
        for (int k2 = 0; k2 < 16; k2++) {
            F4U2 hv; hv.v = hp4[k2];
            ffma2(acc2, whh_per[2*k2],     hv.u[0]);
            ffma2(acc3, whh_per[2*k2 + 1], hv.u[1]);
        }
        // re-arm AFTER the matmul: off the wait->compute critical path
        if (t > 0 && tid == 0) mbar_expect_tx(mbar_a, 64 * 4);

        unsigned long long s01 = fadd2(acc0, acc1);
        unsigned long long s23 = fadd2(acc2, acc3);
        unsigned long long ssum = fadd2(s01, s23);
        float slo, shi;
        unpack2(slo, shi, ssum);
        float a = slo + shi;
        a = (q == 2) ? tanh_fast(a) : sig_fast(a);   // warp-uniform q
        act_s[tid] = a;
        __syncthreads();   // BAR1: gates visible

        if (tid < 64) {
            // c/h update: own gate i (q==0) is the local 'a' -> only 3 LDS
            float cc = fmaf(act_s[64 + jj], creg, a * act_s[128 + jj]);
            creg = cc;
            float hn = act_s[192 + jj] * tanh_fast(cc);
            const int hj = own_off + jj;
            // paired b64 push: halves the mbarrier tx-RMW count
            float hn_p = __shfl_xor_sync(0xFFFFFFFFu, hn, 1);
            if ((jj & 1) == 0)
                st_async_remote_b64(peer_h + (uint32_t)(nxt * H_ + hj) * 4u,
                                    pack2(hn, hn_p), peer_mbar);
            h_s[nxt][hj] = hn;
        } else if (tid < 128 && t < T_ - 1) {
            // conv for y(t+1) from prefetched x
            float v = fmaf(scw[jj*3+2], px2,
                      fmaf(scw[jj*3+1], px1,
                      fmaf(scw[jj*3+0], px0, scb[jj])));
            y_s[jj] = fmaxf(v, 0.f);
            px0 = nx0; px1 = nx1; px2 = nx2;
        }
        if (t > 0) parity ^= 1u;
        __syncthreads();   // BAR2: h own-half + y(t+1) visible
    }

    // final: h(T) in buffer 0 (T even); wait for peer half (parity = 1)
    mbar_wait(mbar_a, parity);

    if (half == 0 && tid < NCLS_) {
        float acc = out_b[tid];
        #pragma unroll 4
        for (int k = 0; k < H_; k++)
            acc = fmaf(h_s[0][k], out_w[tid * H_ + k], acc);
        out[b * NCLS_ + tid] = acc;
    }
    cluster_barrier();   // clean cluster teardown
}

// ---------------- launch ----------------
extern "C" void kernel_launch(void* const* d_in, const int* in_sizes, int n_in,
                              void* d_out, int out_size) {
    const float* x      = (const float*)d_in[0];
    const float* conv_w = (const float*)d_in[1];
    const float* conv_b = (const float*)d_in[2];
    const float* bn_g   = (const float*)d_in[3];
    const float* bn_b   = (const float*)d_in[4];
    const float* w_ih   = (const float*)d_in[5];
    const float* b_ih   = (const float*)d_in[6];
    const float* w_hh   = (const float*)d_in[7];
    const float* b_hh   = (const float*)d_in[8];
    const float* out_w  = (const float*)d_in[9];
    const float* out_b  = (const float*)d_in[10];
    const float* h0     = (const float*)d_in[11];
    const float* c0     = (const float*)d_in[12];
    float* out = (float*)d_out;

    lstm_kernel<<<NCTA_, 256>>>(x, conv_w, conv_b, bn_g, bn_b,
                                w_ih, b_ih, w_hh, b_hh,
                                out_w, out_b, h0, c0, out);
}

// round 17
// speedup vs baseline: 1.1396x; 1.1396x over previous
#include <cuda_runtime.h>
#include <cstdint>

#define B_   64
#define T_   4096
#define H_   128
#define C1_  64
#define NCLS_ 40
#define NCTA_ 128

// ---------------- device scratch (no allocations allowed) ----------------
__device__ float g_part[NCTA_][9];     // per-CTA partial moments of x
__device__ unsigned int g_bar  = 0;    // grid barrier counter (reset in-kernel)
__device__ unsigned int g_done = 0;

// ---------------- helpers ----------------
// single-MUFU tanh (sm_75+): lat ~16 vs ~55 for EX2+RCP chains
__device__ __forceinline__ float tanh_mufu(float v) {
    float r;
    asm("tanh.approx.f32 %0, %1;" : "=f"(r) : "f"(v));
    return r;
}
__device__ __forceinline__ uint32_t smem_u32(const void* p) {
    return (uint32_t)__cvta_generic_to_shared(p);
}
__device__ __forceinline__ uint32_t mapa_u32(uint32_t addr, uint32_t rank) {
    uint32_t r;
    asm("mapa.shared::cluster.u32 %0, %1, %2;" : "=r"(r) : "r"(addr), "r"(rank));
    return r;
}
__device__ __forceinline__ void st_async_remote_f32(uint32_t addr, float v, uint32_t mbar) {
    asm volatile("st.async.shared::cluster.mbarrier::complete_tx::bytes.f32 [%0], %1, [%2];"
                 :: "r"(addr), "f"(v), "r"(mbar) : "memory");
}
__device__ __forceinline__ void mbar_init(uint32_t addr, uint32_t cnt) {
    asm volatile("mbarrier.init.shared.b64 [%0], %1;" :: "r"(addr), "r"(cnt) : "memory");
}
__device__ __forceinline__ void mbar_expect_tx(uint32_t addr, uint32_t bytes) {
    asm volatile("mbarrier.arrive.expect_tx.shared.b64 _, [%0], %1;"
                 :: "r"(addr), "r"(bytes) : "memory");
}
__device__ __forceinline__ void mbar_wait(uint32_t addr, uint32_t parity) {
    asm volatile(
        "{\n\t"
        ".reg .pred P;\n\t"
        "WAITLOOP_%=:\n\t"
        "mbarrier.try_wait.parity.acquire.cta.shared::cta.b64 P, [%0], %1, 0x989680;\n\t"
        "@P bra.uni WAITDONE_%=;\n\t"
        "bra.uni WAITLOOP_%=;\n\t"
        "WAITDONE_%=:\n\t"
        "}\n\t"
        :: "r"(addr), "r"(parity) : "memory");
}
__device__ __forceinline__ void cluster_barrier() {
    asm volatile("barrier.cluster.arrive.aligned;" ::: "memory");
    asm volatile("barrier.cluster.wait.aligned;" ::: "memory");
}
__device__ __forceinline__ unsigned long long pack2(float lo, float hi) {
    unsigned long long u;
    asm("mov.b64 %0, {%1, %2};" : "=l"(u) : "f"(lo), "f"(hi));
    return u;
}
__device__ __forceinline__ void unpack2(float& lo, float& hi, unsigned long long u) {
    asm("mov.b64 {%0, %1}, %2;" : "=f"(lo), "=f"(hi) : "l"(u));
}
__device__ __forceinline__ void ffma2(unsigned long long& acc, unsigned long long a,
                                      unsigned long long b) {
    asm("fma.rn.f32x2 %0, %1, %2, %3;" : "=l"(acc) : "l"(a), "l"(b), "l"(acc));
}
__device__ __forceinline__ unsigned long long fadd2(unsigned long long a,
                                                    unsigned long long b) {
    unsigned long long r;
    asm("add.rn.f32x2 %0, %1, %2;" : "=l"(r) : "l"(a), "l"(b));
    return r;
}
union F4U2 { float4 v; unsigned long long u[2]; };

// ---------------- single fused kernel ----------------
// 128 CTAs, cluster=(2,1,1): blockIdx.x>>1 = batch row, blockIdx.x&1 = hidden half.
// R15 champion structure. Delta: all activations via single-MUFU tanh.approx —
// sigmoid(x) = 0.5*tanh(0.5x)+0.5 (warp-uniform constants, no divergence);
// update-path tanh(c) is one MUFU. Cuts ~80 cyc of serial MUFU chain per step.
__global__ void __cluster_dims__(2, 1, 1) __launch_bounds__(256, 1)
lstm_kernel(const float* __restrict__ x,
            const float* __restrict__ conv_w, const float* __restrict__ conv_b,
            const float* __restrict__ bn_g,   const float* __restrict__ bn_b,
            const float* __restrict__ w_ih, const float* __restrict__ b_ih,
            const float* __restrict__ w_hh, const float* __restrict__ b_hh,
            const float* __restrict__ out_w, const float* __restrict__ out_b,
            const float* __restrict__ h0, const float* __restrict__ c0,
            float* __restrict__ out) {
    __shared__ __align__(16) float h_s[2][H_];   // double-buffered full h
    __shared__ __align__(16) float y_s[C1_];     // conv output (2-BAR safe)
    __shared__ float act_s[256];                 // activated gates
    __shared__ float scw[C1_ * 3];               // folded conv weights
    __shared__ float scb[C1_];
    __shared__ float wred[8][9];
    __shared__ __align__(8) unsigned long long mbar[1];

    const int tid  = threadIdx.x;
    const int b    = blockIdx.x >> 1;
    const int half = blockIdx.x & 1;
    const int lane = tid & 31;
    const int wid  = tid >> 5;

    // ======== prologue A: moments of this CTA's half of row b ========
    {
        float s[9];
        #pragma unroll
        for (int j = 0; j < 9; j++) s[j] = 0.f;
        const float* xr = x + ((size_t)b * T_ + half * (T_ / 2)) * 3;
        #pragma unroll 1
        for (int i = tid; i < T_ / 2; i += 256) {
            float a = xr[i*3+0], bb = xr[i*3+1], c = xr[i*3+2];
            s[0] += a;     s[1] += bb;    s[2] += c;
            s[3] += a*a;   s[4] += a*bb;  s[5] += a*c;
            s[6] += bb*bb; s[7] += bb*c;  s[8] += c*c;
        }
        #pragma unroll
        for (int j = 0; j < 9; j++)
            #pragma unroll
            for (int o = 16; o > 0; o >>= 1)
                s[j] += __shfl_xor_sync(0xFFFFFFFFu, s[j], o);
        if (lane == 0)
            #pragma unroll
            for (int j = 0; j < 9; j++) wred[wid][j] = s[j];
        __syncthreads();
        if (tid < 9) {
            float t = 0.f;
            #pragma unroll
            for (int w = 0; w < 8; w++) t += wred[w][tid];
            g_part[blockIdx.x][tid] = t;
            __threadfence();
        }
        __syncthreads();
        if (tid == 0) atomicAdd(&g_bar, 1u);
    }

    // ======== load LSTM weights (overlaps the grid-barrier wait) ========
    const int q  = tid >> 6;         // gate: 0=i 1=f 2=g 3=o
    const int jj = tid & 63;         // hidden unit within half [0,64)
    const int r  = q * H_ + half * 64 + jj;
    const int own_off  = half * 64;
    const int peer_off = own_off ^ 64;

    unsigned long long whh_own[32], whh_per[32];
    {
        const float2* wo = (const float2*)(w_hh + (size_t)r * H_ + own_off);
        const float2* wp = (const float2*)(w_hh + (size_t)r * H_ + peer_off);
        #pragma unroll
        for (int k = 0; k < 32; k++) {
            float2 a = wo[k]; whh_own[k] = pack2(a.x, a.y);
            float2 c = wp[k]; whh_per[k] = pack2(c.x, c.y);
        }
    }
    unsigned long long wih2[C1_ / 2];
    #pragma unroll
    for (int k = 0; k < C1_ / 2; k++) {
        float2 w = ((const float2*)(w_ih + (size_t)r * C1_))[k];
        wih2[k] = pack2(w.x, w.y);
    }
    const float bias = b_ih[r] + b_hh[r];
    // activation constants (warp-uniform): gate g -> tanh(a); others ->
    // sigmoid(a) = 0.5*tanh(0.5*a) + 0.5
    const float act_k  = (q == 2) ? 1.f : 0.5f;
    const float act_m1 = (q == 2) ? 1.f : 0.5f;
    const float act_m0 = (q == 2) ? 0.f : 0.5f;

    // ======== prologue B: grid barrier + BN fold ========
    if (tid == 0) { while (atomicAdd(&g_bar, 0u) < (unsigned)NCTA_) {} }
    __syncthreads();
    __threadfence();
    if (tid < C1_) {
        float st[9];
        #pragma unroll
        for (int j = 0; j < 9; j++) {
            float t = 0.f;
            #pragma unroll 8
            for (int i = 0; i < NCTA_; i++) t += g_part[i][j];
            st[j] = t;
        }
        const float N = (float)(B_ * T_);
        float m0 = st[0]/N, m1 = st[1]/N, m2 = st[2]/N;
        float C00 = st[3]/N - m0*m0, C01 = st[4]/N - m0*m1, C02 = st[5]/N - m0*m2;
        float C11 = st[6]/N - m1*m1, C12 = st[7]/N - m1*m2, C22 = st[8]/N - m2*m2;
        float w0 = conv_w[tid*3+0], w1 = conv_w[tid*3+1], w2 = conv_w[tid*3+2];
        float mean = w0*m0 + w1*m1 + w2*m2 + conv_b[tid];
        float var  = w0*w0*C00 + w1*w1*C11 + w2*w2*C22
                   + 2.f*(w0*w1*C01 + w0*w2*C02 + w1*w2*C12);
        float sc = bn_g[tid] * rsqrtf(var + 1e-5f);
        scw[tid*3+0] = w0 * sc;
        scw[tid*3+1] = w1 * sc;
        scw[tid*3+2] = w2 * sc;
        scb[tid]     = conv_b[tid] * sc + (bn_b[tid] - mean * sc);
    }
    if (tid == 0) {   // counter reset for the next (graph-replayed) launch
        unsigned d = atomicAdd(&g_done, 1u);
        if (d == (unsigned)(NCTA_ - 1)) { g_bar = 0u; __threadfence(); g_done = 0u; }
    }
    __syncthreads();

    // ======== state init ========
    float creg = 0.f;
    if (tid < 64) creg = c0[b * H_ + half * 64 + tid];
    if (tid < H_) h_s[0][tid] = h0[b * H_ + tid];

    const float* xb = x + (size_t)b * T_ * 3;
    float px0 = 0.f, px1 = 0.f, px2 = 0.f;   // x(t+1) during step t
    if (tid >= 64 && tid < 128) {            // conv lanes, channel jj
        float v = fmaf(scw[jj*3+2], xb[2],
                  fmaf(scw[jj*3+1], xb[1],
                  fmaf(scw[jj*3+0], xb[0], scb[jj])));
        y_s[jj] = fmaxf(v, 0.f);
        px0 = xb[3]; px1 = xb[4]; px2 = xb[5];
    }

    const uint32_t mbar_a    = smem_u32(mbar);
    const uint32_t peer_mbar = mapa_u32(mbar_a, (uint32_t)(half ^ 1));
    const uint32_t peer_h    = mapa_u32(smem_u32(&h_s[0][0]), (uint32_t)(half ^ 1));

    if (tid == 0) mbar_init(mbar_a, 1);
    __syncthreads();
    cluster_barrier();   // mbar init visible cluster-wide before any st.async
    if (tid == 0) mbar_expect_tx(mbar_a, 64 * 4);   // phase 0

    uint32_t parity = 0;

    #pragma unroll 1
    for (int t = 0; t < T_; t++) {
        const int cur = t & 1;
        const int nxt = cur ^ 1;

        // ---- pre-wait: bias + W_ih*y(t) + W_hh_own*h_own(t) ----
        unsigned long long acc0 = pack2(bias, 0.f), acc1 = pack2(0.f, 0.f);
        const float4* y4 = (const float4*)y_s;
        #pragma unroll
        for (int c2 = 0; c2 < C1_ / 4; c2++) {
            F4U2 yv; yv.v = y4[c2];
            ffma2(acc0, wih2[2*c2],     yv.u[0]);
            ffma2(acc1, wih2[2*c2 + 1], yv.u[1]);
        }
        const float4* ho4 = (const float4*)&h_s[cur][own_off];
        #pragma unroll
        for (int k2 = 0; k2 < 16; k2++) {
            F4U2 hv; hv.v = ho4[k2];
            ffma2(acc0, whh_own[2*k2],     hv.u[0]);
            ffma2(acc1, whh_own[2*k2 + 1], hv.u[1]);
        }
        // x(t+2) prefetch issue (consumed next step)
        float nx0 = 0.f, nx1 = 0.f, nx2 = 0.f;
        if (tid >= 64 && tid < 128 && t + 2 < T_) {
            const float* xp = xb + (size_t)(t + 2) * 3;
            nx0 = xp[0]; nx1 = xp[1]; nx2 = xp[2];
        }

        // ---- wait for peer half of h(t) ----
        if (t > 0) mbar_wait(mbar_a, parity);
        // ---- post-wait: peer-half matmul, fresh accumulators ----
        unsigned long long acc2 = pack2(0.f, 0.f), acc3 = pack2(0.f, 0.f);
        const float4* hp4 = (const float4*)&h_s[cur][peer_off];
        #pragma unroll
        for (int k2 = 0; k2 < 16; k2++) {
            F4U2 hv; hv.v = hp4[k2];
            ffma2(acc2, whh_per[2*k2],     hv.u[0]);
            ffma2(acc3, whh_per[2*k2 + 1], hv.u[1]);
        }
        // re-arm AFTER the matmul: off the wait->compute critical path
        if (t > 0 && tid == 0) mbar_expect_tx(mbar_a, 64 * 4);

        unsigned long long s01 = fadd2(acc0, acc1);
        unsigned long long s23 = fadd2(acc2, acc3);
        unsigned long long ssum = fadd2(s01, s23);
        float slo, shi;
        unpack2(slo, shi, ssum);
        float a = slo + shi;
        // single-MUFU activation: t = tanh(k*a); a' = m1*t + m0
        a = fmaf(act_m1, tanh_mufu(act_k * a), act_m0);
        act_s[tid] = a;
        __syncthreads();   // BAR1: gates visible

        if (tid < 64) {
            // c/h update: own gate i (q==0) is the local 'a' -> only 3 LDS
            float cc = fmaf(act_s[64 + jj], creg, a * act_s[128 + jj]);
            creg = cc;
            float hn = act_s[192 + jj] * tanh_mufu(cc);   // one MUFU on the chain
            const int hj = own_off + jj;
            st_async_remote_f32(peer_h + (uint32_t)(nxt * H_ + hj) * 4u, hn, peer_mbar);
            h_s[nxt][hj] = hn;
        } else if (tid < 128 && t < T_ - 1) {
            // conv for y(t+1) from prefetched x
            float v = fmaf(scw[jj*3+2], px2,
                      fmaf(scw[jj*3+1], px1,
                      fmaf(scw[jj*3+0], px0, scb[jj])));
            y_s[jj] = fmaxf(v, 0.f);
            px0 = nx0; px1 = nx1; px2 = nx2;
        }
        if (t > 0) parity ^= 1u;
        __syncthreads();   // BAR2: h own-half + y(t+1) visible
    }

    // final: h(T) in buffer 0 (T even); wait for peer half (parity = 1)
    mbar_wait(mbar_a, parity);

    if (half == 0 && tid < NCLS_) {
        float acc = out_b[tid];
        #pragma unroll 4
        for (int k = 0; k < H_; k++)
            acc = fmaf(h_s[0][k], out_w[tid * H_ + k], acc);
        out[b * NCLS_ + tid] = acc;
    }
    cluster_barrier();   // clean cluster teardown
}

// ---------------- launch ----------------
extern "C" void kernel_launch(void* const* d_in, const int* in_sizes, int n_in,
                              void* d_out, int out_size) {
    const float* x      = (const float*)d_in[0];
    const float* conv_w = (const float*)d_in[1];
    const float* conv_b = (const float*)d_in[2];
    const float* bn_g   = (const float*)d_in[3];
    const float* bn_b   = (const float*)d_in[4];
    const float* w_ih   = (const float*)d_in[5];
    const float* b_ih   = (const float*)d_in[6];
    const float* w_hh   = (const float*)d_in[7];
    const float* b_hh   = (const float*)d_in[8];
    const float* out_w  = (const float*)d_in[9];
    const float* out_b  = (const float*)d_in[10];
    const float* h0     = (const float*)d_in[11];
    const float* c0     = (const float*)d_in[12];
    float* out = (float*)d_out;

    lstm_kernel<<<NCTA_, 256>>>(x, conv_w, conv_b, bn_g, bn_b,
                                w_ih, b_ih, w_hh, b_hh,
                                out_w, out_b, h0, c0, out);
}